// round 1
// baseline (speedup 1.0000x reference)
#include <cuda_runtime.h>

// Problem constants (from reference): B=2, N=8192, T=32, C=64, K=16, NUM_BASES=4
#define Bv 2
#define Nv 8192
#define Tv 32
#define Cv 64
#define Kv 16
#define NB 4

// out[b,n,t,c] = tanh( sum_k z[b, nbr[n,k], t, c] * w[c,n,k] )
// w[c,n,k] = adj[n,k] * sum_base cc[c,base] * bw[base,n,k]
__global__ __launch_bounds__(256)
void geodcd_kernel(const float4* __restrict__ z4,
                   const int*    __restrict__ nbr,
                   const float*  __restrict__ adj,
                   const float*  __restrict__ bw,
                   const float*  __restrict__ cc,
                   float4*       __restrict__ out4)
{
    const int n   = blockIdx.x;
    const int b   = blockIdx.y;
    const int tid = threadIdx.x;   // 256 threads

    __shared__ float ws[Kv * Cv];  // [k][c] effective edge weights (4 KB)
    __shared__ int   snbr[Kv];

    if (tid < Kv) snbr[tid] = nbr[n * Kv + tid];

    // Compute the 16x64 weight tile: 1024 entries, 4 consecutive c per thread.
    {
        const int k  = tid >> 4;          // 0..15
        const int c0 = (tid & 15) << 2;   // 0,4,...,60
        const float a  = adj[n * Kv + k];
        const float w0 = bw[((size_t)0 * Nv + n) * Kv + k];
        const float w1 = bw[((size_t)1 * Nv + n) * Kv + k];
        const float w2 = bw[((size_t)2 * Nv + n) * Kv + k];
        const float w3 = bw[((size_t)3 * Nv + n) * Kv + k];
        #pragma unroll
        for (int j = 0; j < 4; ++j) {
            const int c = c0 + j;
            ws[k * Cv + c] = a * (cc[c * NB + 0] * w0 +
                                  cc[c * NB + 1] * w1 +
                                  cc[c * NB + 2] * w2 +
                                  cc[c * NB + 3] * w3);
        }
    }
    __syncthreads();

    const size_t TC4 = (size_t)Tv * Cv / 4;   // 512 float4 per (b,n) row

    // Hoist the 16 neighbor row base pointers into registers.
    const float4* zp[Kv];
    #pragma unroll
    for (int k = 0; k < Kv; ++k)
        zp[k] = z4 + ((size_t)b * Nv + snbr[k]) * TC4;

    float4* op = out4 + ((size_t)b * Nv + n) * TC4;

    // 512 float4 outputs, 256 threads -> 2 each.
    #pragma unroll
    for (int it = 0; it < 2; ++it) {
        const int s  = tid + it * 256;    // float4 slot: t = s/16, c4 = s%16
        const int c4 = s & 15;
        float4 acc = make_float4(0.f, 0.f, 0.f, 0.f);
        const float4* wrow = reinterpret_cast<const float4*>(ws) + c4;
        #pragma unroll
        for (int k = 0; k < Kv; ++k) {
            const float4 zv = __ldg(zp[k] + s);
            const float4 wv = wrow[k * (Cv / 4)];
            acc.x = fmaf(zv.x, wv.x, acc.x);
            acc.y = fmaf(zv.y, wv.y, acc.y);
            acc.z = fmaf(zv.z, wv.z, acc.z);
            acc.w = fmaf(zv.w, wv.w, acc.w);
        }
        acc.x = tanhf(acc.x);
        acc.y = tanhf(acc.y);
        acc.z = tanhf(acc.z);
        acc.w = tanhf(acc.w);
        op[s] = acc;
    }
}

extern "C" void kernel_launch(void* const* d_in, const int* in_sizes, int n_in,
                              void* d_out, int out_size) {
    // metadata order: z, neighbor_indices, adjacency, basis_weights, channel_coeffs
    const float4* z4  = (const float4*)d_in[0];
    const int*    nbr = (const int*)   d_in[1];
    const float*  adj = (const float*) d_in[2];
    const float*  bw  = (const float*) d_in[3];
    const float*  cc  = (const float*) d_in[4];
    float4*       o4  = (float4*)      d_out;

    dim3 grid(Nv, Bv);   // x = n (fast), y = b -> batch-major wave ordering for L2 residency
    geodcd_kernel<<<grid, 256>>>(z4, nbr, adj, bw, cc, o4);
}

// round 2
// speedup vs baseline: 1.2321x; 1.2321x over previous
#include <cuda_runtime.h>

// Problem constants: B=2, N=8192, T=32, C=64, K=16, NUM_BASES=4
#define Bv 2
#define Nv 8192
#define Tv 32
#define Cv 64
#define Kv 16
#define NB 4
#define TC4 (Tv * Cv / 4)   // 512 float4 per (b,n) row

// out[b,n,t,c] = tanh( sum_k z[b, nbr[n,k], t, c] * w[c,n,k] )
// w[c,n,k] = adj[n,k] * sum_base cc[c,base] * bw[base,n,k]
//
// 128 threads/CTA, each thread owns channel group c4 = tid&15 and 4 output
// slots s = tid + 128*j (same c4 for all j) -> 16 weight LDS.128 per thread
// amortized over 4 outputs. k chunked by 8 to bound register pressure.
__global__ __launch_bounds__(128, 4)
void geodcd_kernel(const float4* __restrict__ z4,
                   const int*    __restrict__ nbr,
                   const float*  __restrict__ adj,
                   const float*  __restrict__ bw,
                   const float*  __restrict__ cc,
                   float4*       __restrict__ out4)
{
    const int n   = blockIdx.x;
    const int b   = blockIdx.y;
    const int tid = threadIdx.x;   // 128 threads

    __shared__ float ws[Kv * Cv];  // [k][c] effective edge weights (4 KB)
    __shared__ int   soff[Kv];     // neighbor row offsets in float4 units

    if (tid < Kv) soff[tid] = nbr[n * Kv + tid] * TC4;

    // Compute the 16x64 weight tile: 1024 entries, 128 threads -> 2 k-rows each.
    {
        const int c0 = (tid & 15) << 2;   // 0,4,...,60
        #pragma unroll
        for (int kk = 0; kk < 2; ++kk) {
            const int k = (tid >> 4) + kk * 8;   // 0..15
            const float a  = adj[n * Kv + k];
            const float w0 = bw[((size_t)0 * Nv + n) * Kv + k];
            const float w1 = bw[((size_t)1 * Nv + n) * Kv + k];
            const float w2 = bw[((size_t)2 * Nv + n) * Kv + k];
            const float w3 = bw[((size_t)3 * Nv + n) * Kv + k];
            #pragma unroll
            for (int j = 0; j < 4; ++j) {
                const int c = c0 + j;
                ws[k * Cv + c] = a * (cc[c * NB + 0] * w0 +
                                      cc[c * NB + 1] * w1 +
                                      cc[c * NB + 2] * w2 +
                                      cc[c * NB + 3] * w3);
            }
        }
    }
    __syncthreads();

    const float4* zb = z4 + (size_t)b * Nv * TC4;
    float4* op = out4 + ((size_t)b * Nv + n) * TC4;
    const int c4 = tid & 15;

    // Neighbor offsets into registers (broadcast LDS.32, cheap).
    int off[Kv];
    #pragma unroll
    for (int k = 0; k < Kv; ++k) off[k] = soff[k];

    const float4* wsr = reinterpret_cast<const float4*>(ws);  // wsr[k*16 + c4]

    float4 acc[4];
    #pragma unroll
    for (int j = 0; j < 4; ++j) acc[j] = make_float4(0.f, 0.f, 0.f, 0.f);

    #pragma unroll
    for (int kc = 0; kc < 2; ++kc) {
        // Weight chunk: 8 float4 in registers, reused across the 4 slots.
        float4 w[8];
        #pragma unroll
        for (int i = 0; i < 8; ++i)
            w[i] = wsr[(kc * 8 + i) * (Cv / 4) + c4];

        #pragma unroll
        for (int j = 0; j < 4; ++j) {
            const int s = tid + j * 128;
            #pragma unroll
            for (int i = 0; i < 8; ++i) {
                const float4 zv = __ldg(zb + off[kc * 8 + i] + s);
                acc[j].x = fmaf(zv.x, w[i].x, acc[j].x);
                acc[j].y = fmaf(zv.y, w[i].y, acc[j].y);
                acc[j].z = fmaf(zv.z, w[i].z, acc[j].z);
                acc[j].w = fmaf(zv.w, w[i].w, acc[j].w);
            }
        }
    }

    #pragma unroll
    for (int j = 0; j < 4; ++j) {
        float4 r;
        r.x = tanhf(acc[j].x);
        r.y = tanhf(acc[j].y);
        r.z = tanhf(acc[j].z);
        r.w = tanhf(acc[j].w);
        op[tid + j * 128] = r;
    }
}

extern "C" void kernel_launch(void* const* d_in, const int* in_sizes, int n_in,
                              void* d_out, int out_size) {
    // metadata order: z, neighbor_indices, adjacency, basis_weights, channel_coeffs
    const float4* z4  = (const float4*)d_in[0];
    const int*    nbr = (const int*)   d_in[1];
    const float*  adj = (const float*) d_in[2];
    const float*  bw  = (const float*) d_in[3];
    const float*  cc  = (const float*) d_in[4];
    float4*       o4  = (float4*)      d_out;

    dim3 grid(Nv, Bv);   // b-major wave ordering keeps one batch's z L2-resident
    geodcd_kernel<<<grid, 128>>>(z4, nbr, adj, bw, cc, o4);
}

// round 3
// speedup vs baseline: 1.2693x; 1.0302x over previous
#include <cuda_runtime.h>

// Problem constants: B=2, N=8192, T=32, C=64, K=16, NUM_BASES=4
#define Bv 2
#define Nv 8192
#define Tv 32
#define Cv 64
#define Kv 16
#define NB 4
#define TC4 (Tv * Cv / 4)   // 512 float4 per (b,n) row

// out[b,n,t,c] = tanh( sum_k z[b, nbr[n,k], t, c] * w[c,n,k] )
// w[c,n,k] = adj[n,k] * sum_base cc[c,base] * bw[base,n,k]
//
// 128 threads/CTA, each thread owns channel group c4 = tid&15 and 4 output
// slots s = tid + 128*j (same c4 for all j) -> weight LDS amortized x4.
// k chunked by 4 (not 8) to keep regs <= 85 so 6 CTAs/SM co-reside.
__global__ __launch_bounds__(128, 6)
void geodcd_kernel(const float4* __restrict__ z4,
                   const int*    __restrict__ nbr,
                   const float*  __restrict__ adj,
                   const float*  __restrict__ bw,
                   const float*  __restrict__ cc,
                   float4*       __restrict__ out4)
{
    const int n   = blockIdx.x;
    const int b   = blockIdx.y;
    const int tid = threadIdx.x;   // 128 threads

    __shared__ float ws[Kv * Cv];  // [k][c] effective edge weights (4 KB)
    __shared__ int   soff[Kv];     // neighbor row offsets in float4 units

    if (tid < Kv) soff[tid] = nbr[n * Kv + tid] * TC4;

    // Compute the 16x64 weight tile: 1024 entries, 128 threads -> 2 k-rows each.
    {
        const int c0 = (tid & 15) << 2;   // 0,4,...,60
        #pragma unroll
        for (int kk = 0; kk < 2; ++kk) {
            const int k = (tid >> 4) + kk * 8;   // 0..15
            const float a  = adj[n * Kv + k];
            const float w0 = bw[((size_t)0 * Nv + n) * Kv + k];
            const float w1 = bw[((size_t)1 * Nv + n) * Kv + k];
            const float w2 = bw[((size_t)2 * Nv + n) * Kv + k];
            const float w3 = bw[((size_t)3 * Nv + n) * Kv + k];
            #pragma unroll
            for (int j = 0; j < 4; ++j) {
                const int c = c0 + j;
                ws[k * Cv + c] = a * (cc[c * NB + 0] * w0 +
                                      cc[c * NB + 1] * w1 +
                                      cc[c * NB + 2] * w2 +
                                      cc[c * NB + 3] * w3);
            }
        }
    }
    __syncthreads();

    const float4* zb = z4 + (size_t)b * Nv * TC4;
    float4* op = out4 + ((size_t)b * Nv + n) * TC4;
    const int c4 = tid & 15;

    // Neighbor offsets into registers (broadcast LDS.32, cheap).
    int off[Kv];
    #pragma unroll
    for (int k = 0; k < Kv; ++k) off[k] = soff[k];

    const float4* wsr = reinterpret_cast<const float4*>(ws);  // wsr[k*16 + c4]

    float4 acc[4];
    #pragma unroll
    for (int j = 0; j < 4; ++j) acc[j] = make_float4(0.f, 0.f, 0.f, 0.f);

    #pragma unroll
    for (int kc = 0; kc < 4; ++kc) {
        // Weight chunk: 4 float4 in registers, reused across the 4 slots.
        float4 w[4];
        #pragma unroll
        for (int i = 0; i < 4; ++i)
            w[i] = wsr[(kc * 4 + i) * (Cv / 4) + c4];

        #pragma unroll
        for (int j = 0; j < 4; ++j) {
            const int s = tid + j * 128;
            #pragma unroll
            for (int i = 0; i < 4; ++i) {
                const float4 zv = __ldg(zb + off[kc * 4 + i] + s);
                acc[j].x = fmaf(zv.x, w[i].x, acc[j].x);
                acc[j].y = fmaf(zv.y, w[i].y, acc[j].y);
                acc[j].z = fmaf(zv.z, w[i].z, acc[j].z);
                acc[j].w = fmaf(zv.w, w[i].w, acc[j].w);
            }
        }
    }

    #pragma unroll
    for (int j = 0; j < 4; ++j) {
        float4 r;
        r.x = tanhf(acc[j].x);
        r.y = tanhf(acc[j].y);
        r.z = tanhf(acc[j].z);
        r.w = tanhf(acc[j].w);
        op[tid + j * 128] = r;
    }
}

extern "C" void kernel_launch(void* const* d_in, const int* in_sizes, int n_in,
                              void* d_out, int out_size) {
    // metadata order: z, neighbor_indices, adjacency, basis_weights, channel_coeffs
    const float4* z4  = (const float4*)d_in[0];
    const int*    nbr = (const int*)   d_in[1];
    const float*  adj = (const float*) d_in[2];
    const float*  bw  = (const float*) d_in[3];
    const float*  cc  = (const float*) d_in[4];
    float4*       o4  = (float4*)      d_out;

    dim3 grid(Nv, Bv);   // b-major wave ordering keeps one batch's z L2-resident
    geodcd_kernel<<<grid, 128>>>(z4, nbr, adj, bw, cc, o4);
}